// round 3
// baseline (speedup 1.0000x reference)
#include <cuda_runtime.h>
#include <math.h>

#define D 128
#define ROWS_PER_BLOCK 64
#define GEMM_THREADS 256

// Scratch: Y = z @ W, [100000, 128] fp32 (51.2 MB). Device global => no allocation.
__device__ float g_Y[100000 * 128];
// 1 if edge_index buffer holds int64, 0 if int32. Set by detect kernel each call.
__device__ int g_idx_is64;

// ---------------------------------------------------------------------------
// Detector: edge_index values are in [0, 100000) (fits in 17 bits). If the
// buffer is int64, every odd 32-bit word (high half, little-endian) of the
// first 1024 entries is 0. If int32, those words are random indices.
// ---------------------------------------------------------------------------
__global__ void detect_idx_dtype(const int* __restrict__ ei32, int n_words)
{
    __shared__ int any_nz;
    if (threadIdx.x == 0) any_nz = 0;
    __syncthreads();
    for (int k = threadIdx.x; k < 1024; k += blockDim.x) {
        int pos = 2 * k + 1;
        if (pos < n_words && ei32[pos] != 0) atomicOr(&any_nz, 1);
    }
    __syncthreads();
    if (threadIdx.x == 0) g_idx_is64 = any_nz ? 0 : 1;
}

// ---------------------------------------------------------------------------
// Kernel 1: Y = z @ W   (N x 128) = (N x 128) @ (128 x 128)
// ---------------------------------------------------------------------------
__global__ __launch_bounds__(GEMM_THREADS) void gemm_zW(
    const float* __restrict__ z, const float* __restrict__ W, int N)
{
    extern __shared__ float smem[];
    float* Ws = smem;                 // [128][128]
    float* zs = smem + D * D;         // [64][128]

    const int tid  = threadIdx.x;
    const int row0 = blockIdx.x * ROWS_PER_BLOCK;

    for (int i = tid * 4; i < D * D; i += GEMM_THREADS * 4)
        *(float4*)(Ws + i) = *(const float4*)(W + i);

    for (int i = tid * 4; i < ROWS_PER_BLOCK * D; i += GEMM_THREADS * 4) {
        const int r  = i >> 7;
        const int gr = row0 + r;
        float4 v = make_float4(0.f, 0.f, 0.f, 0.f);
        if (gr < N) v = *(const float4*)(z + (size_t)gr * D + (i & (D - 1)));
        *(float4*)(zs + i) = v;
    }
    __syncthreads();

    const int cg = tid & 31;
    const int rg = tid >> 5;
    const int c0 = cg * 4;
    const int r0 = rg * 8;

    float acc[8][4];
    #pragma unroll
    for (int r = 0; r < 8; r++)
        #pragma unroll
        for (int c = 0; c < 4; c++) acc[r][c] = 0.f;

    #pragma unroll 4
    for (int d = 0; d < D; d++) {
        const float4 wv = *(const float4*)(Ws + d * D + c0);
        #pragma unroll
        for (int r = 0; r < 8; r++) {
            const float zv = zs[(r0 + r) * D + d];
            acc[r][0] += zv * wv.x;
            acc[r][1] += zv * wv.y;
            acc[r][2] += zv * wv.z;
            acc[r][3] += zv * wv.w;
        }
    }

    #pragma unroll
    for (int r = 0; r < 8; r++) {
        const int gr = row0 + r0 + r;
        if (gr < N) {
            float4 v = make_float4(acc[r][0], acc[r][1], acc[r][2], acc[r][3]);
            *(float4*)(g_Y + (size_t)gr * D + c0) = v;
        }
    }
}

// ---------------------------------------------------------------------------
// Kernel 2: out[e] = sigmoid( dot( Y[edge1[e]], z[edge0[e]] ) )
// One warp per edge; float4 per lane; butterfly reduce. Indices read per the
// detected dtype and clamped to [0, N) as a safety net.
// ---------------------------------------------------------------------------
__global__ __launch_bounds__(512) void edge_decode(
    const float* __restrict__ z, const void* __restrict__ ei_raw,
    float* __restrict__ out, int E, int N)
{
    const int e    = (int)((blockIdx.x * (unsigned)blockDim.x + threadIdx.x) >> 5);
    const int lane = threadIdx.x & 31;
    if (e >= E) return;

    int i, j;
    if (g_idx_is64) {
        const long long* ei = (const long long*)ei_raw;
        i = (int)__ldg(ei + e);
        j = (int)__ldg(ei + (size_t)E + e);
    } else {
        const int* ei = (const int*)ei_raw;
        i = __ldg(ei + e);
        j = __ldg(ei + (size_t)E + e);
    }
    // Safety clamp: no-op for valid inputs, prevents OOB if assumptions break.
    i = min(max(i, 0), N - 1);
    j = min(max(j, 0), N - 1);

    const float4 a = __ldg((const float4*)(g_Y + (size_t)j * D) + lane);
    const float4 b = __ldg((const float4*)(z   + (size_t)i * D) + lane);

    float s = a.x * b.x + a.y * b.y + a.z * b.z + a.w * b.w;
    #pragma unroll
    for (int off = 16; off; off >>= 1)
        s += __shfl_xor_sync(0xffffffffu, s, off);

    if (lane == 0) out[e] = 1.0f / (1.0f + expf(-s));
}

// ---------------------------------------------------------------------------
extern "C" void kernel_launch(void* const* d_in, const int* in_sizes, int n_in,
                              void* d_out, int out_size)
{
    // Identify inputs by element count (all three are distinct):
    //   z: N*128 (largest), edge_index: 2*E (middle), W: 128*128=16384 (smallest)
    int iz = 0, ie = 1, iw = 2;
    {
        // sort indices by size descending: largest=z, middle=edge, smallest=W
        int idx[3] = {0, 1, 2};
        for (int a = 0; a < 2; a++)
            for (int b = a + 1; b < 3; b++)
                if (in_sizes[idx[b]] > in_sizes[idx[a]]) { int t = idx[a]; idx[a] = idx[b]; idx[b] = t; }
        iz = idx[0]; ie = idx[1]; iw = idx[2];
    }

    const float* z   = (const float*)d_in[iz];
    const void*  ei  = d_in[ie];
    const float* W   = (const float*)d_in[iw];
    float*       out = (float*)d_out;

    const int N = in_sizes[iz] / D;   // 100000
    const int E = in_sizes[ie] / 2;   // 625000

    // Detect index dtype (reads only words guaranteed in-bounds for int32).
    detect_idx_dtype<<<1, 256>>>((const int*)ei, in_sizes[ie]);

    const int gemm_smem = (D * D + ROWS_PER_BLOCK * D) * (int)sizeof(float); // 96 KB
    cudaFuncSetAttribute(gemm_zW, cudaFuncAttributeMaxDynamicSharedMemorySize, gemm_smem);

    const int gemm_blocks = (N + ROWS_PER_BLOCK - 1) / ROWS_PER_BLOCK;
    gemm_zW<<<gemm_blocks, GEMM_THREADS, gemm_smem>>>(z, W, N);

    const int edges_per_block = 512 / 32;
    const int edge_blocks = (E + edges_per_block - 1) / edges_per_block;
    edge_decode<<<edge_blocks, 512>>>(z, ei, out, E, N);
}

// round 4
// speedup vs baseline: 1.0883x; 1.0883x over previous
#include <cuda_runtime.h>
#include <cuda_bf16.h>
#include <math.h>

#define D 128
#define GEMM_ROWS 128          // rows per block tile
#define GEMM_THREADS 256       // 8 warps
#define PADW 136               // padded row stride in halves (272B -> conflict-free)

// Scratch: Y = z @ W, [100000, 128] fp32 (51.2 MB). Device global => no allocation.
__device__ float g_Y[100000 * 128];

// ---------------------------------------------------------------------------
// Kernel 1: Y = z @ W via bf16-split tensor-core MMA (Markidis 3-term):
//   a = ah + al (bf16 hi + bf16 residual), b likewise;
//   a*b ≈ ah*bh + ah*bl + al*bh   (error ~2^-17 relative)
// Block: 128 rows x 128 cols. 8 warps, each warp a 16-row strip x 128 cols.
// Smem: z hi/lo [128][136]h, Wt hi/lo [128][136]h (W transposed so the
// col-major B fragment pairs are contiguous). All fragment LDS conflict-free
// by the 272B row padding.
// ---------------------------------------------------------------------------
__global__ __launch_bounds__(GEMM_THREADS) void gemm_zW_tc(
    const float* __restrict__ z, const float* __restrict__ W, int N)
{
    extern __shared__ __nv_bfloat16 sm[];
    __nv_bfloat16* z1 = sm;                    // [128][PADW]
    __nv_bfloat16* z2 = sm + 128 * PADW;
    __nv_bfloat16* w1 = sm + 2 * 128 * PADW;   // transposed: [f][d]
    __nv_bfloat16* w2 = sm + 3 * 128 * PADW;

    const int tid  = threadIdx.x;
    const int row0 = blockIdx.x * GEMM_ROWS;

    // Load + split W, transposed into smem: w1[f][d] = hi(W[d][f])
    for (int idx = tid; idx < D * D; idx += GEMM_THREADS) {
        const int d = idx >> 7, f = idx & 127;
        const float v = W[idx];
        const __nv_bfloat16 h = __float2bfloat16(v);
        const __nv_bfloat16 l = __float2bfloat16(v - __bfloat162float(h));
        w1[f * PADW + d] = h;
        w2[f * PADW + d] = l;
    }
    // Load + split z tile: z1[r][c] = hi(z[row0+r][c])
    for (int idx = tid; idx < GEMM_ROWS * D; idx += GEMM_THREADS) {
        const int r = idx >> 7, c = idx & 127;
        const int gr = row0 + r;
        const float v = (gr < N) ? z[(size_t)gr * D + c] : 0.f;
        const __nv_bfloat16 h = __float2bfloat16(v);
        const __nv_bfloat16 l = __float2bfloat16(v - __bfloat162float(h));
        z1[r * PADW + c] = h;
        z2[r * PADW + c] = l;
    }
    __syncthreads();

    const int warp = tid >> 5;
    const int lane = tid & 31;
    const int g    = lane >> 2;   // group id (0..7)
    const int tig  = lane & 3;    // thread-in-group

    // Accumulators: 16 n-tiles (8 cols each) x 4 f32
    float acc[16][4];
    #pragma unroll
    for (int t = 0; t < 16; t++)
        #pragma unroll
        for (int c = 0; c < 4; c++) acc[t][c] = 0.f;

    const int m0   = warp * 16 + g;       // A frag rows m0, m0+8
    const int rA0  = m0 * PADW;
    const int rA1  = (m0 + 8) * PADW;
    const int cA   = tig * 2;

    #pragma unroll
    for (int ks = 0; ks < 8; ks++) {
        const int k0 = ks * 16;
        // A fragments (hi, lo): reg r0={row g,col k0+cA}, r1={g+8}, r2={g,+8}, r3={g+8,+8}
        unsigned ah0 = *(const unsigned*)(z1 + rA0 + k0 + cA);
        unsigned ah1 = *(const unsigned*)(z1 + rA1 + k0 + cA);
        unsigned ah2 = *(const unsigned*)(z1 + rA0 + k0 + 8 + cA);
        unsigned ah3 = *(const unsigned*)(z1 + rA1 + k0 + 8 + cA);
        unsigned al0 = *(const unsigned*)(z2 + rA0 + k0 + cA);
        unsigned al1 = *(const unsigned*)(z2 + rA1 + k0 + cA);
        unsigned al2 = *(const unsigned*)(z2 + rA0 + k0 + 8 + cA);
        unsigned al3 = *(const unsigned*)(z2 + rA1 + k0 + 8 + cA);

        #pragma unroll
        for (int t = 0; t < 16; t++) {
            const int rB = (t * 8 + g) * PADW + k0 + cA;
            unsigned bh0 = *(const unsigned*)(w1 + rB);
            unsigned bh1 = *(const unsigned*)(w1 + rB + 8);
            unsigned bl0 = *(const unsigned*)(w2 + rB);
            unsigned bl1 = *(const unsigned*)(w2 + rB + 8);

            asm volatile(
                "mma.sync.aligned.m16n8k16.row.col.f32.bf16.bf16.f32 "
                "{%0,%1,%2,%3}, {%4,%5,%6,%7}, {%8,%9}, {%0,%1,%2,%3};\n"
                : "+f"(acc[t][0]), "+f"(acc[t][1]), "+f"(acc[t][2]), "+f"(acc[t][3])
                : "r"(ah0), "r"(ah1), "r"(ah2), "r"(ah3), "r"(bh0), "r"(bh1));
            asm volatile(
                "mma.sync.aligned.m16n8k16.row.col.f32.bf16.bf16.f32 "
                "{%0,%1,%2,%3}, {%4,%5,%6,%7}, {%8,%9}, {%0,%1,%2,%3};\n"
                : "+f"(acc[t][0]), "+f"(acc[t][1]), "+f"(acc[t][2]), "+f"(acc[t][3])
                : "r"(ah0), "r"(ah1), "r"(ah2), "r"(ah3), "r"(bl0), "r"(bl1));
            asm volatile(
                "mma.sync.aligned.m16n8k16.row.col.f32.bf16.bf16.f32 "
                "{%0,%1,%2,%3}, {%4,%5,%6,%7}, {%8,%9}, {%0,%1,%2,%3};\n"
                : "+f"(acc[t][0]), "+f"(acc[t][1]), "+f"(acc[t][2]), "+f"(acc[t][3])
                : "r"(al0), "r"(al1), "r"(al2), "r"(al3), "r"(bh0), "r"(bh1));
        }
    }

    // Store: c0,c1 -> row m0, cols t*8+tig*2; c2,c3 -> row m0+8
    const int gr0 = row0 + m0;
    const int gr1 = gr0 + 8;
    #pragma unroll
    for (int t = 0; t < 16; t++) {
        const int col = t * 8 + tig * 2;
        if (gr0 < N) *(float2*)(g_Y + (size_t)gr0 * D + col) = make_float2(acc[t][0], acc[t][1]);
        if (gr1 < N) *(float2*)(g_Y + (size_t)gr1 * D + col) = make_float2(acc[t][2], acc[t][3]);
    }
}

// ---------------------------------------------------------------------------
// Kernel 2: out[e] = sigmoid( dot( Y[edge1[e]], z[edge0[e]] ) )
// One warp per edge; float4 per lane; butterfly reduce. Index dtype detected
// per-warp (int64 high-words of first 32 entries are all zero; int32 data
// there is random nonzero indices) -> no separate detect launch.
// ---------------------------------------------------------------------------
__global__ __launch_bounds__(512) void edge_decode(
    const float* __restrict__ z, const void* __restrict__ ei_raw,
    float* __restrict__ out, int E, int N)
{
    const int e    = (int)((blockIdx.x * (unsigned)blockDim.x + threadIdx.x) >> 5);
    const int lane = threadIdx.x & 31;

    // dtype probe (uniform across grid; loads hit L1/L2)
    const int probe = __ldg((const int*)ei_raw + 2 * lane + 1);
    const bool is64 = (__ballot_sync(0xffffffffu, probe != 0) == 0u);

    if (e >= E) return;

    int i, j;
    if (is64) {
        const long long* ei = (const long long*)ei_raw;
        i = (int)__ldg(ei + e);
        j = (int)__ldg(ei + (size_t)E + e);
    } else {
        const int* ei = (const int*)ei_raw;
        i = __ldg(ei + e);
        j = __ldg(ei + (size_t)E + e);
    }
    i = min(max(i, 0), N - 1);
    j = min(max(j, 0), N - 1);

    const float4 a = __ldg((const float4*)(g_Y + (size_t)j * D) + lane);
    const float4 b = __ldg((const float4*)(z   + (size_t)i * D) + lane);

    float s = a.x * b.x + a.y * b.y + a.z * b.z + a.w * b.w;
    #pragma unroll
    for (int off = 16; off; off >>= 1)
        s += __shfl_xor_sync(0xffffffffu, s, off);

    if (lane == 0) out[e] = 1.0f / (1.0f + expf(-s));
}

// ---------------------------------------------------------------------------
extern "C" void kernel_launch(void* const* d_in, const int* in_sizes, int n_in,
                              void* d_out, int out_size)
{
    // Identify inputs by element count (z: N*128 largest, ei: 2*E middle, W: 16384 smallest)
    int idx[3] = {0, 1, 2};
    for (int a = 0; a < 2; a++)
        for (int b = a + 1; b < 3; b++)
            if (in_sizes[idx[b]] > in_sizes[idx[a]]) { int t = idx[a]; idx[a] = idx[b]; idx[b] = t; }
    const int iz = idx[0], ie = idx[1], iw = idx[2];

    const float* z   = (const float*)d_in[iz];
    const void*  ei  = d_in[ie];
    const float* W   = (const float*)d_in[iw];
    float*       out = (float*)d_out;

    const int N = in_sizes[iz] / D;   // 100000
    const int E = in_sizes[ie] / 2;   // 625000

    const int gemm_smem = 4 * 128 * PADW * (int)sizeof(__nv_bfloat16);  // 139264 B
    cudaFuncSetAttribute(gemm_zW_tc, cudaFuncAttributeMaxDynamicSharedMemorySize, gemm_smem);

    const int gemm_blocks = (N + GEMM_ROWS - 1) / GEMM_ROWS;
    gemm_zW_tc<<<gemm_blocks, GEMM_THREADS, gemm_smem>>>(z, W, N);

    const int edges_per_block = 512 / 32;
    const int edge_blocks = (E + edges_per_block - 1) / edges_per_block;
    edge_decode<<<edge_blocks, 512>>>(z, ei, out, E, N);
}

// round 5
// speedup vs baseline: 1.7445x; 1.6029x over previous
#include <cuda_runtime.h>
#include <cuda_bf16.h>
#include <math.h>

#define D 128
#define GEMM_ROWS 64           // rows per block tile
#define GEMM_THREADS 256       // 8 warps: 4 row-strips x 2 col-halves
#define PADW 136               // padded row stride in bf16 units (272B)

// Scratch: Y = z @ W, [100000, 128] fp32 (51.2 MB). Device global => no allocation.
__device__ float g_Y[100000 * 128];

// ---------------------------------------------------------------------------
// Kernel 1: Y = z @ W via bf16-split tensor-core MMA (Markidis 3-term).
// Block: 64 rows x 128 cols, 8 warps. warp&3 -> 16-row strip, warp>>2 -> 64-col half.
// Smem: z hi/lo [64][136], Wt hi/lo [128][136] = 104448 B -> 2 blocks/SM.
// ---------------------------------------------------------------------------
__global__ __launch_bounds__(GEMM_THREADS) void gemm_zW_tc(
    const float* __restrict__ z, const float* __restrict__ W, int N)
{
    extern __shared__ __nv_bfloat16 sm[];
    __nv_bfloat16* z1 = sm;                               // [64][PADW]
    __nv_bfloat16* z2 = sm + GEMM_ROWS * PADW;
    __nv_bfloat16* w1 = sm + 2 * GEMM_ROWS * PADW;        // transposed: [f][d]
    __nv_bfloat16* w2 = sm + 2 * GEMM_ROWS * PADW + 128 * PADW;

    const int tid  = threadIdx.x;
    const int row0 = blockIdx.x * GEMM_ROWS;

    // Load + split W, transposed into smem: w1[f][d] = hi(W[d][f])
    for (int idx = tid; idx < D * D; idx += GEMM_THREADS) {
        const int d = idx >> 7, f = idx & 127;
        const float v = W[idx];
        const __nv_bfloat16 h = __float2bfloat16(v);
        const __nv_bfloat16 l = __float2bfloat16(v - __bfloat162float(h));
        w1[f * PADW + d] = h;
        w2[f * PADW + d] = l;
    }
    // Load + split z tile
    for (int idx = tid; idx < GEMM_ROWS * D; idx += GEMM_THREADS) {
        const int r = idx >> 7, c = idx & 127;
        const int gr = row0 + r;
        const float v = (gr < N) ? z[(size_t)gr * D + c] : 0.f;
        const __nv_bfloat16 h = __float2bfloat16(v);
        const __nv_bfloat16 l = __float2bfloat16(v - __bfloat162float(h));
        z1[r * PADW + c] = h;
        z2[r * PADW + c] = l;
    }
    __syncthreads();

    const int warp = tid >> 5;
    const int lane = tid & 31;
    const int g    = lane >> 2;   // group id (0..7)
    const int tig  = lane & 3;    // thread-in-group
    const int wr   = warp & 3;    // row strip
    const int wc   = warp >> 2;   // col half (0/1)

    float acc[8][4];
    #pragma unroll
    for (int t = 0; t < 8; t++)
        #pragma unroll
        for (int c = 0; c < 4; c++) acc[t][c] = 0.f;

    const int m0   = wr * 16 + g;         // A frag rows m0, m0+8
    const int rA0  = m0 * PADW;
    const int rA1  = (m0 + 8) * PADW;
    const int cA   = tig * 2;

    #pragma unroll
    for (int ks = 0; ks < 8; ks++) {
        const int k0 = ks * 16;
        unsigned ah0 = *(const unsigned*)(z1 + rA0 + k0 + cA);
        unsigned ah1 = *(const unsigned*)(z1 + rA1 + k0 + cA);
        unsigned ah2 = *(const unsigned*)(z1 + rA0 + k0 + 8 + cA);
        unsigned ah3 = *(const unsigned*)(z1 + rA1 + k0 + 8 + cA);
        unsigned al0 = *(const unsigned*)(z2 + rA0 + k0 + cA);
        unsigned al1 = *(const unsigned*)(z2 + rA1 + k0 + cA);
        unsigned al2 = *(const unsigned*)(z2 + rA0 + k0 + 8 + cA);
        unsigned al3 = *(const unsigned*)(z2 + rA1 + k0 + 8 + cA);

        #pragma unroll
        for (int tt = 0; tt < 8; tt++) {
            const int t  = wc * 8 + tt;           // global n-tile
            const int rB = (t * 8 + g) * PADW + k0 + cA;
            unsigned bh0 = *(const unsigned*)(w1 + rB);
            unsigned bh1 = *(const unsigned*)(w1 + rB + 8);
            unsigned bl0 = *(const unsigned*)(w2 + rB);
            unsigned bl1 = *(const unsigned*)(w2 + rB + 8);

            asm volatile(
                "mma.sync.aligned.m16n8k16.row.col.f32.bf16.bf16.f32 "
                "{%0,%1,%2,%3}, {%4,%5,%6,%7}, {%8,%9}, {%0,%1,%2,%3};\n"
                : "+f"(acc[tt][0]), "+f"(acc[tt][1]), "+f"(acc[tt][2]), "+f"(acc[tt][3])
                : "r"(ah0), "r"(ah1), "r"(ah2), "r"(ah3), "r"(bh0), "r"(bh1));
            asm volatile(
                "mma.sync.aligned.m16n8k16.row.col.f32.bf16.bf16.f32 "
                "{%0,%1,%2,%3}, {%4,%5,%6,%7}, {%8,%9}, {%0,%1,%2,%3};\n"
                : "+f"(acc[tt][0]), "+f"(acc[tt][1]), "+f"(acc[tt][2]), "+f"(acc[tt][3])
                : "r"(ah0), "r"(ah1), "r"(ah2), "r"(ah3), "r"(bl0), "r"(bl1));
            asm volatile(
                "mma.sync.aligned.m16n8k16.row.col.f32.bf16.bf16.f32 "
                "{%0,%1,%2,%3}, {%4,%5,%6,%7}, {%8,%9}, {%0,%1,%2,%3};\n"
                : "+f"(acc[tt][0]), "+f"(acc[tt][1]), "+f"(acc[tt][2]), "+f"(acc[tt][3])
                : "r"(al0), "r"(al1), "r"(al2), "r"(al3), "r"(bh0), "r"(bh1));
        }
    }

    const int gr0 = row0 + m0;
    const int gr1 = gr0 + 8;
    #pragma unroll
    for (int tt = 0; tt < 8; tt++) {
        const int col = (wc * 8 + tt) * 8 + tig * 2;
        if (gr0 < N) *(float2*)(g_Y + (size_t)gr0 * D + col) = make_float2(acc[tt][0], acc[tt][1]);
        if (gr1 < N) *(float2*)(g_Y + (size_t)gr1 * D + col) = make_float2(acc[tt][2], acc[tt][3]);
    }
}

// ---------------------------------------------------------------------------
// Kernel 2: out[e] = sigmoid( dot( Y[edge1[e]], z[edge0[e]] ) )
// 4 edges per warp, 8 lanes per edge, 8 independent float4 gathers per thread
// (MLP=8). Coalesced: for load k, the 8 lanes of a group read one 128B line.
// ---------------------------------------------------------------------------
__global__ __launch_bounds__(256) void edge_decode(
    const float* __restrict__ z, const void* __restrict__ ei_raw,
    float* __restrict__ out, int E, int N)
{
    const int lane  = threadIdx.x & 31;
    const int gwarp = (blockIdx.x * 256 + threadIdx.x) >> 5;
    const int sub   = lane >> 3;      // which of the warp's 4 edges
    const int lane8 = lane & 7;

    // dtype probe (full-warp, before any divergence)
    const int probe = __ldg((const int*)ei_raw + 2 * lane + 1);
    const bool is64 = (__ballot_sync(0xffffffffu, probe != 0) == 0u);

    const int e_real = gwarp * 4 + sub;
    const int e      = min(e_real, E - 1);   // clamp: keeps full warp active

    int i, j;
    if (is64) {
        const long long* ei = (const long long*)ei_raw;
        i = (int)__ldg(ei + e);
        j = (int)__ldg(ei + (size_t)E + e);
    } else {
        const int* ei = (const int*)ei_raw;
        i = __ldg(ei + e);
        j = __ldg(ei + (size_t)E + e);
    }
    i = min(max(i, 0), N - 1);
    j = min(max(j, 0), N - 1);

    const float4* Yrow = (const float4*)(g_Y + (size_t)j * D);
    const float4* zrow = (const float4*)(z   + (size_t)i * D);

    float4 a[4], b[4];
    #pragma unroll
    for (int k = 0; k < 4; k++) a[k] = __ldg(Yrow + k * 8 + lane8);
    #pragma unroll
    for (int k = 0; k < 4; k++) b[k] = __ldg(zrow + k * 8 + lane8);

    float s = 0.f;
    #pragma unroll
    for (int k = 0; k < 4; k++)
        s += a[k].x * b[k].x + a[k].y * b[k].y + a[k].z * b[k].z + a[k].w * b[k].w;

    s += __shfl_xor_sync(0xffffffffu, s, 4);
    s += __shfl_xor_sync(0xffffffffu, s, 2);
    s += __shfl_xor_sync(0xffffffffu, s, 1);

    if (lane8 == 0 && e_real < E) out[e_real] = 1.0f / (1.0f + expf(-s));
}

// ---------------------------------------------------------------------------
extern "C" void kernel_launch(void* const* d_in, const int* in_sizes, int n_in,
                              void* d_out, int out_size)
{
    // Identify inputs by element count (z: N*128 largest, ei: 2*E middle, W: 16384 smallest)
    int idx[3] = {0, 1, 2};
    for (int a = 0; a < 2; a++)
        for (int b = a + 1; b < 3; b++)
            if (in_sizes[idx[b]] > in_sizes[idx[a]]) { int t = idx[a]; idx[a] = idx[b]; idx[b] = t; }
    const int iz = idx[0], ie = idx[1], iw = idx[2];

    const float* z   = (const float*)d_in[iz];
    const void*  ei  = d_in[ie];
    const float* W   = (const float*)d_in[iw];
    float*       out = (float*)d_out;

    const int N = in_sizes[iz] / D;   // 100000
    const int E = in_sizes[ie] / 2;   // 625000

    const int gemm_smem = (2 * GEMM_ROWS + 2 * 128) * PADW * (int)sizeof(__nv_bfloat16); // 104448
    cudaFuncSetAttribute(gemm_zW_tc, cudaFuncAttributeMaxDynamicSharedMemorySize, gemm_smem);

    const int gemm_blocks = (N + GEMM_ROWS - 1) / GEMM_ROWS;
    gemm_zW_tc<<<gemm_blocks, GEMM_THREADS, gemm_smem>>>(z, W, N);

    const int edges_per_block = (256 / 32) * 4;   // 32
    const int edge_blocks = (E + edges_per_block - 1) / edges_per_block;
    edge_decode<<<edge_blocks, 256>>>(z, ei, out, E, N);
}

// round 7
// speedup vs baseline: 2.1183x; 1.2143x over previous
#include <cuda_runtime.h>
#include <cuda_bf16.h>
#include <cstdint>
#include <math.h>

#define D 128
#define GEMM_ROWS 64           // rows per block tile
#define GEMM_THREADS 256       // 8 warps: 4 row-strips x 2 col-halves
#define PADW 136               // padded row stride in bf16 units (272B, 16B-multiple)

// Scratch (device globals => no allocation):
__device__ float g_Y[100000 * 128];                 // Y = z @ W, fp32
__device__ __nv_bfloat16 g_w1t[128 * 128];          // hi(W) transposed: [f][d]
__device__ __nv_bfloat16 g_w2t[128 * 128];          // lo(W) transposed

#define LDSM4(r0, r1, r2, r3, addr)                                          \
    asm volatile("ldmatrix.sync.aligned.m8n8.x4.shared.b16 {%0,%1,%2,%3}, [%4];" \
                 : "=r"(r0), "=r"(r1), "=r"(r2), "=r"(r3) : "r"(addr))

// ---------------------------------------------------------------------------
// Pre-split W: W[d][f] fp32 -> g_w1t[f][d], g_w2t[f][d] bf16 hi/lo. 16384 elems.
// ---------------------------------------------------------------------------
__global__ void split_W(const float* __restrict__ W)
{
    const int idx = blockIdx.x * blockDim.x + threadIdx.x;
    if (idx < D * D) {
        const int d = idx >> 7, f = idx & 127;
        const float v = W[idx];
        const __nv_bfloat16 h = __float2bfloat16(v);
        const __nv_bfloat16 l = __float2bfloat16(v - __bfloat162float(h));
        g_w1t[f * D + d] = h;
        g_w2t[f * D + d] = l;
    }
}

// ---------------------------------------------------------------------------
// Kernel 1: Y = z @ W via bf16-split MMA (Markidis 3-term), ldmatrix frags.
// Block: 64 rows x 128 cols, 8 warps (4 row-strips x 2 col-halves).
// Smem: z hi/lo [64][136], Wt hi/lo [128][136] = 104448 B -> 2 blocks/SM.
// ---------------------------------------------------------------------------
__global__ __launch_bounds__(GEMM_THREADS) void gemm_zW_tc(
    const float* __restrict__ z, int N)
{
    extern __shared__ __nv_bfloat16 sm[];
    __nv_bfloat16* z1 = sm;                               // [64][PADW]
    __nv_bfloat16* z2 = sm + GEMM_ROWS * PADW;
    __nv_bfloat16* w1 = sm + 2 * GEMM_ROWS * PADW;        // [f][d] transposed
    __nv_bfloat16* w2 = sm + 2 * GEMM_ROWS * PADW + 128 * PADW;

    const int tid  = threadIdx.x;
    const int row0 = blockIdx.x * GEMM_ROWS;

    // W: straight vectorized copy of pre-split bf16 (uint4 = 8 bf16)
    {
        const uint4* s1 = (const uint4*)g_w1t;
        const uint4* s2 = (const uint4*)g_w2t;
        for (int i = tid; i < 128 * 16; i += GEMM_THREADS) {
            const int f = i >> 4, c8 = (i & 15) * 8;
            *(uint4*)(w1 + f * PADW + c8) = s1[i];
            *(uint4*)(w2 + f * PADW + c8) = s2[i];
        }
    }
    // z tile: float4 loads, split, packed bf16x2 stores
    for (int i = tid; i < GEMM_ROWS * 32; i += GEMM_THREADS) {
        const int r = i >> 5, c = (i & 31) * 4;
        const int gr = row0 + r;
        float4 v = make_float4(0.f, 0.f, 0.f, 0.f);
        if (gr < N) v = *(const float4*)(z + (size_t)gr * D + c);

        const __nv_bfloat16 h0 = __float2bfloat16(v.x), h1 = __float2bfloat16(v.y);
        const __nv_bfloat16 h2 = __float2bfloat16(v.z), h3 = __float2bfloat16(v.w);
        const __nv_bfloat16 l0 = __float2bfloat16(v.x - __bfloat162float(h0));
        const __nv_bfloat16 l1 = __float2bfloat16(v.y - __bfloat162float(h1));
        const __nv_bfloat16 l2 = __float2bfloat16(v.z - __bfloat162float(h2));
        const __nv_bfloat16 l3 = __float2bfloat16(v.w - __bfloat162float(h3));

        uint2 hp, lp;
        hp.x = (unsigned)__bfloat16_as_ushort(h0) | ((unsigned)__bfloat16_as_ushort(h1) << 16);
        hp.y = (unsigned)__bfloat16_as_ushort(h2) | ((unsigned)__bfloat16_as_ushort(h3) << 16);
        lp.x = (unsigned)__bfloat16_as_ushort(l0) | ((unsigned)__bfloat16_as_ushort(l1) << 16);
        lp.y = (unsigned)__bfloat16_as_ushort(l2) | ((unsigned)__bfloat16_as_ushort(l3) << 16);
        *(uint2*)(z1 + r * PADW + c) = hp;
        *(uint2*)(z2 + r * PADW + c) = lp;
    }
    __syncthreads();

    const int warp = tid >> 5;
    const int lane = tid & 31;
    const int wr   = warp & 3;    // row strip
    const int wc   = warp >> 2;   // col half (0/1)

    float acc[8][4];
    #pragma unroll
    for (int t = 0; t < 8; t++)
        #pragma unroll
        for (int c = 0; c < 4; c++) acc[t][c] = 0.f;

    // Shared-space base addresses (bytes)
    const uint32_t base = (uint32_t)__cvta_generic_to_shared(sm);
    const uint32_t z1s = base;
    const uint32_t z2s = base + GEMM_ROWS * PADW * 2;
    const uint32_t w1s = base + 2 * GEMM_ROWS * PADW * 2;
    const uint32_t w2s = w1s + 128 * PADW * 2;

    // A lane address: row = wr*16 + (lane&15), col = (lane>>4)*8 (+k0)
    const uint32_t aoff = (uint32_t)(((wr * 16 + (lane & 15)) * PADW + (lane >> 4) * 8) * 2);
    // B lane address: tile_sel = lane>>3: bit1 -> +8 n-rows (next tt), bit0 -> +8 k
    const uint32_t boff = (uint32_t)((((lane & 7) + (lane >> 4) * 8) * PADW + ((lane >> 3) & 1) * 8) * 2);

    #pragma unroll
    for (int ks = 0; ks < 8; ks++) {
        const int k0 = ks * 16;
        unsigned ah0, ah1, ah2, ah3, al0, al1, al2, al3;
        LDSM4(ah0, ah1, ah2, ah3, z1s + aoff + k0 * 2);
        LDSM4(al0, al1, al2, al3, z2s + aoff + k0 * 2);

        #pragma unroll
        for (int p = 0; p < 4; p++) {                 // tt pair: tt = 2p, 2p+1
            const uint32_t nk = (uint32_t)(((wc * 8 + 2 * p) * 8 * PADW + k0) * 2);
            unsigned bh0, bh1, bh2, bh3, bl0, bl1, bl2, bl3;
            LDSM4(bh0, bh1, bh2, bh3, w1s + boff + nk);
            LDSM4(bl0, bl1, bl2, bl3, w2s + boff + nk);

            #pragma unroll
            for (int q = 0; q < 2; q++) {             // q=0 -> tt=2p, q=1 -> tt=2p+1
                const int tt = 2 * p + q;
                const unsigned Bh0 = q ? bh2 : bh0, Bh1 = q ? bh3 : bh1;
                const unsigned Bl0 = q ? bl2 : bl0, Bl1 = q ? bl3 : bl1;
                asm volatile(
                    "mma.sync.aligned.m16n8k16.row.col.f32.bf16.bf16.f32 "
                    "{%0,%1,%2,%3}, {%4,%5,%6,%7}, {%8,%9}, {%0,%1,%2,%3};\n"
                    : "+f"(acc[tt][0]), "+f"(acc[tt][1]), "+f"(acc[tt][2]), "+f"(acc[tt][3])
                    : "r"(ah0), "r"(ah1), "r"(ah2), "r"(ah3), "r"(Bh0), "r"(Bh1));
                asm volatile(
                    "mma.sync.aligned.m16n8k16.row.col.f32.bf16.bf16.f32 "
                    "{%0,%1,%2,%3}, {%4,%5,%6,%7}, {%8,%9}, {%0,%1,%2,%3};\n"
                    : "+f"(acc[tt][0]), "+f"(acc[tt][1]), "+f"(acc[tt][2]), "+f"(acc[tt][3])
                    : "r"(ah0), "r"(ah1), "r"(ah2), "r"(ah3), "r"(Bl0), "r"(Bl1));
                asm volatile(
                    "mma.sync.aligned.m16n8k16.row.col.f32.bf16.bf16.f32 "
                    "{%0,%1,%2,%3}, {%4,%5,%6,%7}, {%8,%9}, {%0,%1,%2,%3};\n"
                    : "+f"(acc[tt][0]), "+f"(acc[tt][1]), "+f"(acc[tt][2]), "+f"(acc[tt][3])
                    : "r"(al0), "r"(al1), "r"(al2), "r"(al3), "r"(Bh0), "r"(Bh1));
            }
        }
    }

    // Store: lane g = lane>>2 rows, tig = lane&3 col pairs (same as R5 mapping)
    const int g   = lane >> 2;
    const int tig = lane & 3;
    const int gr0 = row0 + wr * 16 + g;
    const int gr1 = gr0 + 8;
    #pragma unroll
    for (int tt = 0; tt < 8; tt++) {
        const int col = (wc * 8 + tt) * 8 + tig * 2;
        if (gr0 < N) *(float2*)(g_Y + (size_t)gr0 * D + col) = make_float2(acc[tt][0], acc[tt][1]);
        if (gr1 < N) *(float2*)(g_Y + (size_t)gr1 * D + col) = make_float2(acc[tt][2], acc[tt][3]);
    }
}

// ---------------------------------------------------------------------------
// Kernel 2: out[e] = sigmoid( dot( Y[edge1[e]], z[edge0[e]] ) )
// 4 edges per warp, 8 lanes per edge, MLP=8 float4 gathers per thread.
// ---------------------------------------------------------------------------
__global__ __launch_bounds__(256) void edge_decode(
    const float* __restrict__ z, const void* __restrict__ ei_raw,
    float* __restrict__ out, int E, int N)
{
    const int lane  = threadIdx.x & 31;
    const int gwarp = (blockIdx.x * 256 + threadIdx.x) >> 5;
    const int sub   = lane >> 3;
    const int lane8 = lane & 7;

    const int probe = __ldg((const int*)ei_raw + 2 * lane + 1);
    const bool is64 = (__ballot_sync(0xffffffffu, probe != 0) == 0u);

    const int e_real = gwarp * 4 + sub;
    const int e      = min(e_real, E - 1);

    int i, j;
    if (is64) {
        const long long* ei = (const long long*)ei_raw;
        i = (int)__ldg(ei + e);
        j = (int)__ldg(ei + (size_t)E + e);
    } else {
        const int* ei = (const int*)ei_raw;
        i = __ldg(ei + e);
        j = __ldg(ei + (size_t)E + e);
    }
    i = min(max(i, 0), N - 1);
    j = min(max(j, 0), N - 1);

    const float4* Yrow = (const float4*)(g_Y + (size_t)j * D);
    const float4* zrow = (const float4*)(z   + (size_t)i * D);

    float4 a[4], b[4];
    #pragma unroll
    for (int k = 0; k < 4; k++) a[k] = __ldg(Yrow + k * 8 + lane8);
    #pragma unroll
    for (int k = 0; k < 4; k++) b[k] = __ldg(zrow + k * 8 + lane8);

    float s = 0.f;
    #pragma unroll
    for (int k = 0; k < 4; k++)
        s += a[k].x * b[k].x + a[k].y * b[k].y + a[k].z * b[k].z + a[k].w * b[k].w;

    s += __shfl_xor_sync(0xffffffffu, s, 4);
    s += __shfl_xor_sync(0xffffffffu, s, 2);
    s += __shfl_xor_sync(0xffffffffu, s, 1);

    if (lane8 == 0 && e_real < E) out[e_real] = 1.0f / (1.0f + expf(-s));
}

// ---------------------------------------------------------------------------
extern "C" void kernel_launch(void* const* d_in, const int* in_sizes, int n_in,
                              void* d_out, int out_size)
{
    // Identify inputs by element count (z: N*128 largest, ei: 2*E middle, W: 16384 smallest)
    int idx[3] = {0, 1, 2};
    for (int a = 0; a < 2; a++)
        for (int b = a + 1; b < 3; b++)
            if (in_sizes[idx[b]] > in_sizes[idx[a]]) { int t = idx[a]; idx[a] = idx[b]; idx[b] = t; }
    const int iz = idx[0], ie = idx[1], iw = idx[2];

    const float* z   = (const float*)d_in[iz];
    const void*  ei  = d_in[ie];
    const float* W   = (const float*)d_in[iw];
    float*       out = (float*)d_out;

    const int N = in_sizes[iz] / D;   // 100000
    const int E = in_sizes[ie] / 2;   // 625000

    split_W<<<(D * D + 255) / 256, 256>>>(W);

    const int gemm_smem = (2 * GEMM_ROWS + 2 * 128) * PADW * (int)sizeof(__nv_bfloat16); // 104448
    cudaFuncSetAttribute(gemm_zW_tc, cudaFuncAttributeMaxDynamicSharedMemorySize, gemm_smem);

    const int gemm_blocks = (N + GEMM_ROWS - 1) / GEMM_ROWS;
    gemm_zW_tc<<<gemm_blocks, GEMM_THREADS, gemm_smem>>>(z, N);

    const int edges_per_block = (256 / 32) * 4;   // 32
    const int edge_blocks = (E + edges_per_block - 1) / edges_per_block;
    edge_decode<<<edge_blocks, 256>>>(z, ei, out, E, N);
}

// round 9
// speedup vs baseline: 2.6325x; 1.2427x over previous
#include <cuda_runtime.h>
#include <cuda_bf16.h>
#include <cstdint>
#include <math.h>

#define D 128
#define GEMM_ROWS 64           // rows per tile
#define GEMM_THREADS 256       // 8 warps: 4 row-strips x 2 col-halves
#define PADW 136               // padded row stride in bf16 units (272B, 16B-multiple)
#define GEMM_BLOCKS 296        // persistent: 2 blocks/SM x 148 SMs

// Scratch (device globals => no allocation):
__device__ float g_Y[100000 * 128];                 // Y = z @ W, fp32
__device__ __nv_bfloat16 g_w1t[128 * 128];          // hi(W) transposed: [f][d]
__device__ __nv_bfloat16 g_w2t[128 * 128];          // lo(W) transposed

#define LDSM4(r0, r1, r2, r3, addr)                                          \
    asm volatile("ldmatrix.sync.aligned.m8n8.x4.shared.b16 {%0,%1,%2,%3}, [%4];" \
                 : "=r"(r0), "=r"(r1), "=r"(r2), "=r"(r3) : "r"(addr))

// ---------------------------------------------------------------------------
// Pre-split W: W[d][f] fp32 -> g_w1t[f][d], g_w2t[f][d] bf16 hi/lo.
// ---------------------------------------------------------------------------
__global__ void split_W(const float* __restrict__ W)
{
    const int idx = blockIdx.x * blockDim.x + threadIdx.x;
    if (idx < D * D) {
        const int d = idx >> 7, f = idx & 127;
        const float v = W[idx];
        const __nv_bfloat16 h = __float2bfloat16(v);
        const __nv_bfloat16 l = __float2bfloat16(v - __bfloat162float(h));
        g_w1t[f * D + d] = h;
        g_w2t[f * D + d] = l;
    }
}

// ---------------------------------------------------------------------------
// Kernel 1 (persistent): Y = z @ W via bf16-split MMA (Markidis 3-term),
// ldmatrix fragments. Each block loads W into smem ONCE, then loops over
// 64-row z tiles with stride gridDim.x.
// Smem: z hi/lo [64][136], Wt hi/lo [128][136] = 104448 B -> 2 blocks/SM.
// ---------------------------------------------------------------------------
__global__ __launch_bounds__(GEMM_THREADS) void gemm_zW_tc(
    const float* __restrict__ z, int N, int n_tiles)
{
    extern __shared__ __nv_bfloat16 sm[];
    __nv_bfloat16* z1 = sm;                               // [64][PADW]
    __nv_bfloat16* z2 = sm + GEMM_ROWS * PADW;
    __nv_bfloat16* w1 = sm + 2 * GEMM_ROWS * PADW;        // [f][d] transposed
    __nv_bfloat16* w2 = sm + 2 * GEMM_ROWS * PADW + 128 * PADW;

    const int tid  = threadIdx.x;
    const int warp = tid >> 5;
    const int lane = tid & 31;
    const int wr   = warp & 3;    // row strip
    const int wc   = warp >> 2;   // col half (0/1)

    // W: one-time vectorized copy of pre-split bf16 (uint4 = 8 bf16)
    {
        const uint4* s1 = (const uint4*)g_w1t;
        const uint4* s2 = (const uint4*)g_w2t;
        for (int i = tid; i < 128 * 16; i += GEMM_THREADS) {
            const int f = i >> 4, c8 = (i & 15) * 8;
            *(uint4*)(w1 + f * PADW + c8) = s1[i];
            *(uint4*)(w2 + f * PADW + c8) = s2[i];
        }
    }

    // Shared-space base addresses (bytes)
    const uint32_t base = (uint32_t)__cvta_generic_to_shared(sm);
    const uint32_t z1s = base;
    const uint32_t z2s = base + GEMM_ROWS * PADW * 2;
    const uint32_t w1s = base + 2 * GEMM_ROWS * PADW * 2;
    const uint32_t w2s = w1s + 128 * PADW * 2;

    // A lane address: row = wr*16 + (lane&15), col = (lane>>4)*8 (+k0)
    const uint32_t aoff = (uint32_t)(((wr * 16 + (lane & 15)) * PADW + (lane >> 4) * 8) * 2);
    // B lane address: lane>>3 bit0 -> +8 k, bit1 -> next 8 n-rows (next tt)
    const uint32_t boff = (uint32_t)((((lane & 7) + (lane >> 4) * 8) * PADW + ((lane >> 3) & 1) * 8) * 2);

    const int g   = lane >> 2;
    const int tig = lane & 3;

    for (int tile = blockIdx.x; tile < n_tiles; tile += GEMM_BLOCKS) {
        const int row0 = tile * GEMM_ROWS;

        __syncthreads();   // WAR: previous tile's LDSM reads done before z overwrite

        // z tile: float4 loads, split, packed bf16x2 stores
        for (int i = tid; i < GEMM_ROWS * 32; i += GEMM_THREADS) {
            const int r = i >> 5, c = (i & 31) * 4;
            const int gr = row0 + r;
            float4 v = make_float4(0.f, 0.f, 0.f, 0.f);
            if (gr < N) v = *(const float4*)(z + (size_t)gr * D + c);

            const __nv_bfloat16 h0 = __float2bfloat16(v.x), h1 = __float2bfloat16(v.y);
            const __nv_bfloat16 h2 = __float2bfloat16(v.z), h3 = __float2bfloat16(v.w);
            const __nv_bfloat16 l0 = __float2bfloat16(v.x - __bfloat162float(h0));
            const __nv_bfloat16 l1 = __float2bfloat16(v.y - __bfloat162float(h1));
            const __nv_bfloat16 l2 = __float2bfloat16(v.z - __bfloat162float(h2));
            const __nv_bfloat16 l3 = __float2bfloat16(v.w - __bfloat162float(h3));

            uint2 hp, lp;
            hp.x = (unsigned)__bfloat16_as_ushort(h0) | ((unsigned)__bfloat16_as_ushort(h1) << 16);
            hp.y = (unsigned)__bfloat16_as_ushort(h2) | ((unsigned)__bfloat16_as_ushort(h3) << 16);
            lp.x = (unsigned)__bfloat16_as_ushort(l0) | ((unsigned)__bfloat16_as_ushort(l1) << 16);
            lp.y = (unsigned)__bfloat16_as_ushort(l2) | ((unsigned)__bfloat16_as_ushort(l3) << 16);
            *(uint2*)(z1 + r * PADW + c) = hp;
            *(uint2*)(z2 + r * PADW + c) = lp;
        }
        __syncthreads();

        float acc[8][4];
        #pragma unroll
        for (int t = 0; t < 8; t++)
            #pragma unroll
            for (int c = 0; c < 4; c++) acc[t][c] = 0.f;

        #pragma unroll
        for (int ks = 0; ks < 8; ks++) {
            const int k0 = ks * 16;
            unsigned ah0, ah1, ah2, ah3, al0, al1, al2, al3;
            LDSM4(ah0, ah1, ah2, ah3, z1s + aoff + k0 * 2);
            LDSM4(al0, al1, al2, al3, z2s + aoff + k0 * 2);

            #pragma unroll
            for (int p = 0; p < 4; p++) {
                const uint32_t nk = (uint32_t)(((wc * 8 + 2 * p) * 8 * PADW + k0) * 2);
                unsigned bh0, bh1, bh2, bh3, bl0, bl1, bl2, bl3;
                LDSM4(bh0, bh1, bh2, bh3, w1s + boff + nk);
                LDSM4(bl0, bl1, bl2, bl3, w2s + boff + nk);

                #pragma unroll
                for (int q = 0; q < 2; q++) {
                    const int tt = 2 * p + q;
                    const unsigned Bh0 = q ? bh2 : bh0, Bh1 = q ? bh3 : bh1;
                    const unsigned Bl0 = q ? bl2 : bl0, Bl1 = q ? bl3 : bl1;
                    asm volatile(
                        "mma.sync.aligned.m16n8k16.row.col.f32.bf16.bf16.f32 "
                        "{%0,%1,%2,%3}, {%4,%5,%6,%7}, {%8,%9}, {%0,%1,%2,%3};\n"
                        : "+f"(acc[tt][0]), "+f"(acc[tt][1]), "+f"(acc[tt][2]), "+f"(acc[tt][3])
                        : "r"(ah0), "r"(ah1), "r"(ah2), "r"(ah3), "r"(Bh0), "r"(Bh1));
                    asm volatile(
                        "mma.sync.aligned.m16n8k16.row.col.f32.bf16.bf16.f32 "
                        "{%0,%1,%2,%3}, {%4,%5,%6,%7}, {%8,%9}, {%0,%1,%2,%3};\n"
                        : "+f"(acc[tt][0]), "+f"(acc[tt][1]), "+f"(acc[tt][2]), "+f"(acc[tt][3])
                        : "r"(ah0), "r"(ah1), "r"(ah2), "r"(ah3), "r"(Bl0), "r"(Bl1));
                    asm volatile(
                        "mma.sync.aligned.m16n8k16.row.col.f32.bf16.bf16.f32 "
                        "{%0,%1,%2,%3}, {%4,%5,%6,%7}, {%8,%9}, {%0,%1,%2,%3};\n"
                        : "+f"(acc[tt][0]), "+f"(acc[tt][1]), "+f"(acc[tt][2]), "+f"(acc[tt][3])
                        : "r"(al0), "r"(al1), "r"(al2), "r"(al3), "r"(Bh0), "r"(Bh1));
                }
            }
        }

        // Store (overlaps next tile's loads; barrier at loop head covers WAR)
        const int gr0 = row0 + wr * 16 + g;
        const int gr1 = gr0 + 8;
        #pragma unroll
        for (int tt = 0; tt < 8; tt++) {
            const int col = (wc * 8 + tt) * 8 + tig * 2;
            if (gr0 < N) *(float2*)(g_Y + (size_t)gr0 * D + col) = make_float2(acc[tt][0], acc[tt][1]);
            if (gr1 < N) *(float2*)(g_Y + (size_t)gr1 * D + col) = make_float2(acc[tt][2], acc[tt][3]);
        }
    }
}

// ---------------------------------------------------------------------------
// Kernel 2: out[e] = sigmoid( dot( Y[edge1[e]], z[edge0[e]] ) )
// 4 edges per warp, 8 lanes per edge, MLP=8 float4 gathers per thread.
// ---------------------------------------------------------------------------
__global__ __launch_bounds__(256) void edge_decode(
    const float* __restrict__ z, const void* __restrict__ ei_raw,
    float* __restrict__ out, int E, int N)
{
    const int lane  = threadIdx.x & 31;
    const int gwarp = (blockIdx.x * 256 + threadIdx.x) >> 5;
    const int sub   = lane >> 3;
    const int lane8 = lane & 7;

    const int probe = __ldg((const int*)ei_raw + 2 * lane + 1);
    const bool is64 = (__ballot_sync(0xffffffffu, probe != 0) == 0u);

    const int e_real = gwarp * 4 + sub;
    const int e      = min(e_real, E - 1);

    int i, j;
    if (is64) {
        const long long* ei = (const long long*)ei_raw;
        i = (int)__ldg(ei + e);
        j = (int)__ldg(ei + (size_t)E + e);
    } else {
        const int* ei = (const int*)ei_raw;
        i = __ldg(ei + e);
        j = __ldg(ei + (size_t)E + e);
    }
    i = min(max(i, 0), N - 1);
    j = min(max(j, 0), N - 1);

    const float4* Yrow = (const float4*)(g_Y + (size_t)j * D);
    const float4* zrow = (const float4*)(z   + (size_t)i * D);

    float4 a[4], b[4];
    #pragma unroll
    for (int k = 0; k < 4; k++) a[k] = __ldg(Yrow + k * 8 + lane8);
    #pragma unroll
    for (int k = 0; k < 4; k++) b[k] = __ldg(zrow + k * 8 + lane8);

    float s = 0.f;
    #pragma unroll
    for (int k = 0; k < 4; k++)
        s += a[k].x * b[k].x + a[k].y * b[k].y + a[k].z * b[k].z + a[k].w * b[k].w;

    s += __shfl_xor_sync(0xffffffffu, s, 4);
    s += __shfl_xor_sync(0xffffffffu, s, 2);
    s += __shfl_xor_sync(0xffffffffu, s, 1);

    if (lane8 == 0 && e_real < E) out[e_real] = 1.0f / (1.0f + expf(-s));
}

// ---------------------------------------------------------------------------
extern "C" void kernel_launch(void* const* d_in, const int* in_sizes, int n_in,
                              void* d_out, int out_size)
{
    // Identify inputs by element count (z: N*128 largest, ei: 2*E middle, W: 16384 smallest)
    int idx[3] = {0, 1, 2};
    for (int a = 0; a < 2; a++)
        for (int b = a + 1; b < 3; b++)
            if (in_sizes[idx[b]] > in_sizes[idx[a]]) { int t = idx[a]; idx[a] = idx[b]; idx[b] = t; }
    const int iz = idx[0], ie = idx[1], iw = idx[2];

    const float* z   = (const float*)d_in[iz];
    const void*  ei  = d_in[ie];
    const float* W   = (const float*)d_in[iw];
    float*       out = (float*)d_out;

    const int N = in_sizes[iz] / D;   // 100000
    const int E = in_sizes[ie] / 2;   // 625000

    split_W<<<(D * D + 255) / 256, 256>>>(W);

    const int n_tiles = (N + GEMM_ROWS - 1) / GEMM_ROWS;
    const int gemm_smem = (2 * GEMM_ROWS + 2 * 128) * PADW * (int)sizeof(__nv_bfloat16); // 104448
    cudaFuncSetAttribute(gemm_zW_tc, cudaFuncAttributeMaxDynamicSharedMemorySize, gemm_smem);
    gemm_zW_tc<<<GEMM_BLOCKS, GEMM_THREADS, gemm_smem>>>(z, N, n_tiles);

    const int edges_per_block = (256 / 32) * 4;   // 32
    const int edge_blocks = (E + edges_per_block - 1) / edges_per_block;
    edge_decode<<<edge_blocks, 256>>>(z, ei, out, E, N);
}